// round 2
// baseline (speedup 1.0000x reference)
#include <cuda_runtime.h>
#include <math.h>

#define B 4
#define N 64
#define T 256
#define H 256
#define L 5
#define TOPK 8
#define BT (B*T)

__constant__ int c_lags[L] = {1, 5, 10, 21, 30};

// -------- scratch (device globals: no allocation allowed) --------
__device__ float g_W[H*H];      // wq^T @ wk
__device__ float g_btil[H];     // bq @ wk
__device__ float g_v[H];        // wq^T @ bk
__device__ float g_c0;          // bq . bk
__device__ float g_wvT[H*H];
__device__ float g_w1T[H*H];
__device__ float g_w2T[H*H];
__device__ float g_Qt[BT*H];    // Q tilde
__device__ float g_c[BT];       // Q . bk per row
__device__ float g_agg[BT*H];   // weighted sum of selected peer rows
__device__ float g_sw[BT];      // sum of weights

// =============== prep: W = wq^T wk, biases folded, transposes ===============
__global__ void k_prep(const float* __restrict__ wq, const float* __restrict__ wk,
                       const float* __restrict__ bq, const float* __restrict__ bk,
                       const float* __restrict__ wv, const float* __restrict__ w1,
                       const float* __restrict__ w2) {
    int bidx = blockIdx.x;
    int j = threadIdx.x;
    if (bidx < H) {
        int h = bidx;
        float acc = 0.f;
        for (int m = 0; m < H; m++) acc += wq[m*H + h] * wk[m*H + j];
        g_W[h*H + j]   = acc;
        g_wvT[h*H + j] = wv[j*H + h];
        g_w1T[h*H + j] = w1[j*H + h];
        g_w2T[h*H + j] = w2[j*H + h];
    } else if (bidx == H) {
        float acc = 0.f;
        for (int m = 0; m < H; m++) acc += bq[m] * wk[m*H + j];
        g_btil[j] = acc;
    } else if (bidx == H + 1) {
        float acc = 0.f;
        for (int m = 0; m < H; m++) acc += wq[m*H + j] * bk[m];
        g_v[j] = acc;
    } else {
        if (j < 32) {
            float s = 0.f;
            for (int i = j; i < H; i += 32) s += bq[i] * bk[i];
            for (int off = 16; off; off >>= 1) s += __shfl_down_sync(0xffffffffu, s, off);
            if (j == 0) g_c0 = s;
        }
    }
}

// =============== Qtilde = target_h @ W + btil ; c = target_h.v + c0 ==========
#define RB2 16
__global__ void k_qtilde(const float* __restrict__ x) {
    __shared__ float xs[RB2*H];
    int r0 = blockIdx.x * RB2;
    for (int i = threadIdx.x; i < RB2*H; i += 256) xs[i] = x[r0*H + i];
    __syncthreads();
    int j = threadIdx.x;
    float acc[RB2];
    float bt = g_btil[j];
    #pragma unroll
    for (int r = 0; r < RB2; r++) acc[r] = bt;
    for (int h = 0; h < H; h++) {
        float w = g_W[h*H + j];
        #pragma unroll
        for (int r = 0; r < RB2; r++) acc[r] += xs[r*H + h] * w;
    }
    #pragma unroll
    for (int r = 0; r < RB2; r++) g_Qt[(r0 + r)*H + j] = acc[r];

    int wid = threadIdx.x >> 5, lane = threadIdx.x & 31;
    float c0 = g_c0;
    for (int r = wid; r < RB2; r += 8) {
        float s = 0.f;
        for (int h = lane; h < H; h += 32) s += xs[r*H + h] * g_v[h];
        for (int off = 16; off; off >>= 1) s += __shfl_down_sync(0xffffffffu, s, off);
        if (lane == 0) g_c[r0 + r] = s + c0;
    }
}

// ===== logits = (Qt . peer[lagged] + c)/16, mask, top-8, softmax, aggregate ==
// mask read as 4-byte words (nonzero test) — correct for int32 OR float32 storage.
__global__ void k_logits(const float* __restrict__ peer,
                         const int* __restrict__ mask) {
    int bt = blockIdx.x;
    int b = bt >> 8;          // T = 256
    int t = bt & 255;
    __shared__ float qrow[H];
    __shared__ float lg[N*L];
    __shared__ float swt[TOPK];
    __shared__ int   sidx[TOPK];
    __shared__ float scbt;
    int tid = threadIdx.x;
    qrow[tid] = g_Qt[bt*H + tid];
    if (tid == 0) scbt = g_c[bt];
    __syncthreads();
    float cbt = scbt;
    int wid = tid >> 5, lane = tid & 31;
    const float4* q4 = (const float4*)qrow;

    for (int d = wid; d < N*L; d += 8) {
        int n = d / L, l = d - n*L;
        int tp = t - c_lags[l];
        bool ok = (tp >= 0) && (mask[(b << 6) + n] != 0);
        float val;
        if (ok) {
            const float4* p4 = (const float4*)(peer + ((size_t)((b*N + n)*T + tp)) * H);
            float s = 0.f;
            #pragma unroll
            for (int i = 0; i < 2; i++) {
                float4 pv = p4[lane + 32*i];
                float4 qv = q4[lane + 32*i];
                s += pv.x*qv.x + pv.y*qv.y + pv.z*qv.z + pv.w*qv.w;
            }
            for (int off = 16; off; off >>= 1) s += __shfl_down_sync(0xffffffffu, s, off);
            val = (s + cbt) * 0.0625f;
        } else {
            val = -INFINITY;
        }
        if (lane == 0) lg[d] = val;
    }
    __syncthreads();

    if (wid == 0) {
        float vals[TOPK];
        for (int k = 0; k < TOPK; k++) {
            float bv = -INFINITY; int bi = 0x7fffffff;
            for (int i = lane; i < N*L; i += 32) {
                float v = lg[i];
                if (v > bv || (v == bv && i < bi)) { bv = v; bi = i; }
            }
            for (int off = 16; off; off >>= 1) {
                float ov = __shfl_down_sync(0xffffffffu, bv, off);
                int   oi = __shfl_down_sync(0xffffffffu, bi, off);
                if (ov > bv || (ov == bv && oi < bi)) { bv = ov; bi = oi; }
            }
            bi = __shfl_sync(0xffffffffu, bi, 0);
            bv = __shfl_sync(0xffffffffu, bv, 0);
            if (lane == 0) { sidx[k] = bi; vals[k] = bv; lg[bi] = -INFINITY; }
            __syncwarp();
        }
        if (lane == 0) {
            float m = -INFINITY;
            bool allinf = true;
            float safe[TOPK];
            #pragma unroll
            for (int k = 0; k < TOPK; k++) {
                bool ii = isinf(vals[k]);
                allinf = allinf && ii;
                safe[k] = ii ? -1e9f : vals[k];
                if (safe[k] > m) m = safe[k];
            }
            float sw_ = 0.f;
            if (allinf) {
                #pragma unroll
                for (int k = 0; k < TOPK; k++) swt[k] = 0.f;
            } else {
                float e[TOPK]; float tot = 0.f;
                #pragma unroll
                for (int k = 0; k < TOPK; k++) { e[k] = expf(safe[k] - m); tot += e[k]; }
                #pragma unroll
                for (int k = 0; k < TOPK; k++) { float w = e[k] / tot; swt[k] = w; sw_ += w; }
            }
            g_sw[bt] = sw_;
        }
    }
    __syncthreads();

    float acc = 0.f;
    #pragma unroll
    for (int k = 0; k < TOPK; k++) {
        float w = swt[k];
        if (w != 0.f) {
            int d = sidx[k];
            int n = d / L, l = d - n*L;
            int tp = t - c_lags[l];
            acc += w * peer[((size_t)((b*N + n)*T + tp)) * H + tid];
        }
    }
    g_agg[bt*H + tid] = acc;
}

// ===== cs_y = agg@wv^T + sw*bv ; FFN(elu) ; residual ; LayerNorm ; out ======
#define RB3 8
__global__ void k_ffn(const float* __restrict__ bv, const float* __restrict__ b1,
                      const float* __restrict__ b2, const float* __restrict__ gamma,
                      const float* __restrict__ beta, float* __restrict__ out) {
    __shared__ float s_a[RB3*H];    // agg, later y
    __shared__ float s_cs[RB3*H];   // cs_y
    __shared__ float s_h[RB3*H];    // elu hidden
    __shared__ float s_sw[RB3];
    __shared__ float s_mu[RB3], s_rs[RB3];
    int r0 = blockIdx.x * RB3;
    int tid = threadIdx.x;
    for (int i = tid; i < RB3*H; i += 256) s_a[i] = g_agg[r0*H + i];
    if (tid < RB3) s_sw[tid] = g_sw[r0 + tid];
    __syncthreads();
    int j = tid;
    float acc[RB3];

    // GEMM1: cs = agg @ wv^T + sw*bv
    {
        float bvj = bv[j];
        #pragma unroll
        for (int r = 0; r < RB3; r++) acc[r] = s_sw[r] * bvj;
        for (int h = 0; h < H; h++) {
            float w = g_wvT[h*H + j];
            #pragma unroll
            for (int r = 0; r < RB3; r++) acc[r] += s_a[r*H + h] * w;
        }
        #pragma unroll
        for (int r = 0; r < RB3; r++) s_cs[r*H + j] = acc[r];
    }
    __syncthreads();
    // GEMM2: hidden = elu(cs @ w1^T + b1)
    {
        float b1j = b1[j];
        #pragma unroll
        for (int r = 0; r < RB3; r++) acc[r] = b1j;
        for (int h = 0; h < H; h++) {
            float w = g_w1T[h*H + j];
            #pragma unroll
            for (int r = 0; r < RB3; r++) acc[r] += s_cs[r*H + h] * w;
        }
        #pragma unroll
        for (int r = 0; r < RB3; r++) {
            float x = acc[r];
            s_h[r*H + j] = x > 0.f ? x : expm1f(x);
        }
    }
    __syncthreads();
    // GEMM3: y = cs + hidden @ w2^T + b2  (store into s_a)
    {
        float b2j = b2[j];
        #pragma unroll
        for (int r = 0; r < RB3; r++) acc[r] = b2j + s_cs[r*H + j];
        for (int h = 0; h < H; h++) {
            float w = g_w2T[h*H + j];
            #pragma unroll
            for (int r = 0; r < RB3; r++) acc[r] += s_h[r*H + h] * w;
        }
        #pragma unroll
        for (int r = 0; r < RB3; r++) s_a[r*H + j] = acc[r];
    }
    __syncthreads();
    // LayerNorm: one warp per row
    {
        int wid = tid >> 5, lane = tid & 31;
        int r = wid;
        float s = 0.f, q = 0.f;
        for (int i = lane; i < H; i += 32) { float v = s_a[r*H + i]; s += v; q += v*v; }
        for (int off = 16; off; off >>= 1) {
            s += __shfl_down_sync(0xffffffffu, s, off);
            q += __shfl_down_sync(0xffffffffu, q, off);
        }
        if (lane == 0) {
            float mu = s * (1.f/H);
            float var = q * (1.f/H) - mu*mu;
            s_mu[r] = mu;
            s_rs[r] = rsqrtf(var + 1e-5f);
        }
    }
    __syncthreads();
    float gj = gamma[j], bj = beta[j];
    #pragma unroll
    for (int r = 0; r < RB3; r++)
        out[(r0 + r)*H + j] = (s_a[r*H + j] - s_mu[r]) * s_rs[r] * gj + bj;
}

extern "C" void kernel_launch(void* const* d_in, const int* in_sizes, int n_in,
                              void* d_out, int out_size) {
    const float* target_h = (const float*)d_in[0];
    const float* peer_h   = (const float*)d_in[1];
    const int*   peer_mask = (const int*)d_in[2];
    const float* wq = (const float*)d_in[3];
    const float* bq = (const float*)d_in[4];
    const float* wk = (const float*)d_in[5];
    const float* bk = (const float*)d_in[6];
    const float* wv = (const float*)d_in[7];
    const float* bv = (const float*)d_in[8];
    const float* w1 = (const float*)d_in[9];
    const float* b1 = (const float*)d_in[10];
    const float* w2 = (const float*)d_in[11];
    const float* b2 = (const float*)d_in[12];
    const float* gamma = (const float*)d_in[13];
    const float* beta  = (const float*)d_in[14];
    float* out = (float*)d_out;

    k_prep<<<H + 3, 256>>>(wq, wk, bq, bk, wv, w1, w2);
    k_qtilde<<<BT/RB2, 256>>>(target_h);
    k_logits<<<BT, 256>>>(peer_h, peer_mask);
    k_ffn<<<BT/RB3, 256>>>(bv, b1, b2, gamma, beta, out);
}

// round 4
// speedup vs baseline: 1.4043x; 1.4043x over previous
#include <cuda_runtime.h>
#include <math.h>

#define B 4
#define N 64
#define T 256
#define H 256
#define L 5
#define TOPK 8
#define BT (B*T)

#define RB 8            // rows per block in GEMM kernels
#define KK 8            // k-tile for weight staging
#define NT (H/KK)       // 32 tiles

__constant__ int c_lags[L] = {1, 5, 10, 21, 30};

// -------- scratch (device globals: no allocation allowed) --------
__device__ float g_W[H*H];      // wq^T @ wk
__device__ float g_btil[H];     // bq @ wk
__device__ float g_v[H];        // wq^T @ bk
__device__ float g_c0;          // bq . bk
__device__ float g_wvT[H*H];
__device__ float g_w1T[H*H];
__device__ float g_w2T[H*H];
__device__ float g_Qt[BT*H];    // Q tilde
__device__ float g_c[BT];       // Q . bk per row
__device__ float g_agg[BT*H];   // weighted sum of selected peer rows
__device__ float g_sw[BT];      // sum of weights

// Double-buffered smem-staged GEMM: thread j accumulates 8 rows for column j.
// XT: transposed activations xT[h*RB + r]. SW: staging buffer [2][KK*H].
#define GEMM8(Wg, XT, SW, ACC) do {                                         \
    float _tmp[KK];                                                         \
    _Pragma("unroll")                                                       \
    for (int hh = 0; hh < KK; hh++) _tmp[hh] = (Wg)[hh*H + j];              \
    _Pragma("unroll")                                                       \
    for (int hh = 0; hh < KK; hh++) (SW)[0][hh*H + j] = _tmp[hh];           \
    __syncthreads();                                                        \
    for (int kt = 0; kt < NT; kt++) {                                       \
        int _cur = kt & 1;                                                  \
        if (kt + 1 < NT) {                                                  \
            _Pragma("unroll")                                               \
            for (int hh = 0; hh < KK; hh++)                                 \
                _tmp[hh] = (Wg)[(kt+1)*KK*H + hh*H + j];                    \
        }                                                                   \
        int _k0 = kt * KK;                                                  \
        _Pragma("unroll")                                                   \
        for (int hh = 0; hh < KK; hh++) {                                   \
            float _w = (SW)[_cur][hh*H + j];                                \
            float4 _x0 = *(const float4*)&(XT)[(_k0+hh)*RB];                \
            float4 _x1 = *(const float4*)&(XT)[(_k0+hh)*RB + 4];            \
            ACC[0] += _x0.x*_w; ACC[1] += _x0.y*_w;                         \
            ACC[2] += _x0.z*_w; ACC[3] += _x0.w*_w;                         \
            ACC[4] += _x1.x*_w; ACC[5] += _x1.y*_w;                         \
            ACC[6] += _x1.z*_w; ACC[7] += _x1.w*_w;                         \
        }                                                                   \
        if (kt + 1 < NT) {                                                  \
            _Pragma("unroll")                                               \
            for (int hh = 0; hh < KK; hh++)                                 \
                (SW)[(kt+1)&1][hh*H + j] = _tmp[hh];                        \
        }                                                                   \
        __syncthreads();                                                    \
    }                                                                       \
} while (0)

// =============== prep: W = wq^T wk, biases folded, transposes ===============
__global__ void k_prep(const float* __restrict__ wq, const float* __restrict__ wk,
                       const float* __restrict__ bq, const float* __restrict__ bk,
                       const float* __restrict__ wv, const float* __restrict__ w1,
                       const float* __restrict__ w2) {
    int bidx = blockIdx.x;
    int j = threadIdx.x;
    if (bidx < H) {
        int h = bidx;
        float acc = 0.f;
        for (int m = 0; m < H; m++) acc += wq[m*H + h] * wk[m*H + j];
        g_W[h*H + j]   = acc;
        g_wvT[h*H + j] = wv[j*H + h];
        g_w1T[h*H + j] = w1[j*H + h];
        g_w2T[h*H + j] = w2[j*H + h];
    } else if (bidx == H) {
        float acc = 0.f;
        for (int m = 0; m < H; m++) acc += bq[m] * wk[m*H + j];
        g_btil[j] = acc;
    } else if (bidx == H + 1) {
        float acc = 0.f;
        for (int m = 0; m < H; m++) acc += wq[m*H + j] * bk[m];
        g_v[j] = acc;
    } else {
        if (j < 32) {
            float s = 0.f;
            for (int i = j; i < H; i += 32) s += bq[i] * bk[i];
            for (int off = 16; off; off >>= 1) s += __shfl_down_sync(0xffffffffu, s, off);
            if (j == 0) g_c0 = s;
        }
    }
}

// ========= Qtilde = target_h @ W + btil ; c = target_h . v + c0 =============
__global__ void k_qtilde(const float* __restrict__ x) {
    __shared__ float s_x[H*RB];         // transposed input
    __shared__ float s_w[2][KK*H];
    __shared__ float s_part[8][RB];     // per-warp partials for c
    int r0 = blockIdx.x * RB;
    int tid = threadIdx.x;
    int j = tid;
    int wid = tid >> 5, lane = tid & 31;

    float v[RB];
    #pragma unroll
    for (int r = 0; r < RB; r++) v[r] = x[(r0 + r)*H + tid];
    *(float4*)&s_x[tid*RB]     = make_float4(v[0], v[1], v[2], v[3]);
    *(float4*)&s_x[tid*RB + 4] = make_float4(v[4], v[5], v[6], v[7]);

    // c partials: v[r] * g_v[tid], reduced across all 256 threads
    float gv = g_v[tid];
    #pragma unroll
    for (int r = 0; r < RB; r++) {
        float s = v[r] * gv;
        for (int off = 16; off; off >>= 1) s += __shfl_down_sync(0xffffffffu, s, off);
        if (lane == 0) s_part[wid][r] = s;
    }
    __syncthreads();
    if (tid < RB) {
        float s = g_c0;
        #pragma unroll
        for (int w = 0; w < 8; w++) s += s_part[w][tid];
        g_c[r0 + tid] = s;
    }

    float acc[RB];
    float bt = g_btil[j];
    #pragma unroll
    for (int r = 0; r < RB; r++) acc[r] = bt;
    GEMM8(g_W, s_x, s_w, acc);
    #pragma unroll
    for (int r = 0; r < RB; r++) g_Qt[(r0 + r)*H + j] = acc[r];
}

// ===== logits = (Qt . peer[lagged] + c)/16, mask, top-8, softmax, aggregate ==
__global__ void k_logits(const float* __restrict__ peer,
                         const int* __restrict__ mask) {
    int bt = blockIdx.x;
    int b = bt >> 8;          // T = 256
    int t = bt & 255;
    __shared__ float qrow[H];
    __shared__ float lg[N*L];
    __shared__ float swt[TOPK];
    __shared__ int   sidx[TOPK];
    __shared__ float scbt;
    int tid = threadIdx.x;
    qrow[tid] = g_Qt[bt*H + tid];
    if (tid == 0) scbt = g_c[bt];
    __syncthreads();
    float cbt = scbt;
    int wid = tid >> 5, lane = tid & 31;
    const float4* q4 = (const float4*)qrow;

    for (int d = wid; d < N*L; d += 8) {
        int n = d / L, l = d - n*L;
        int tp = t - c_lags[l];
        bool ok = (tp >= 0) && (mask[(b << 6) + n] != 0);
        float val;
        if (ok) {
            const float4* p4 = (const float4*)(peer + ((size_t)((b*N + n)*T + tp)) * H);
            float s = 0.f;
            #pragma unroll
            for (int i = 0; i < 2; i++) {
                float4 pv = p4[lane + 32*i];
                float4 qv = q4[lane + 32*i];
                s += pv.x*qv.x + pv.y*qv.y + pv.z*qv.z + pv.w*qv.w;
            }
            for (int off = 16; off; off >>= 1) s += __shfl_down_sync(0xffffffffu, s, off);
            val = (s + cbt) * 0.0625f;
        } else {
            val = -INFINITY;
        }
        if (lane == 0) lg[d] = val;
    }
    __syncthreads();

    if (wid == 0) {
        float vals[TOPK];
        for (int k = 0; k < TOPK; k++) {
            float bv = -INFINITY; int bi = 0x7fffffff;
            for (int i = lane; i < N*L; i += 32) {
                float v = lg[i];
                if (v > bv || (v == bv && i < bi)) { bv = v; bi = i; }
            }
            for (int off = 16; off; off >>= 1) {
                float ov = __shfl_down_sync(0xffffffffu, bv, off);
                int   oi = __shfl_down_sync(0xffffffffu, bi, off);
                if (ov > bv || (ov == bv && oi < bi)) { bv = ov; bi = oi; }
            }
            bi = __shfl_sync(0xffffffffu, bi, 0);
            bv = __shfl_sync(0xffffffffu, bv, 0);
            if (lane == 0) { sidx[k] = bi; vals[k] = bv; lg[bi] = -INFINITY; }
            __syncwarp();
        }
        if (lane == 0) {
            float m = -INFINITY;
            bool allinf = true;
            float safe[TOPK];
            #pragma unroll
            for (int k = 0; k < TOPK; k++) {
                bool ii = isinf(vals[k]);
                allinf = allinf && ii;
                safe[k] = ii ? -1e9f : vals[k];
                if (safe[k] > m) m = safe[k];
            }
            float sw_ = 0.f;
            if (allinf) {
                #pragma unroll
                for (int k = 0; k < TOPK; k++) swt[k] = 0.f;
            } else {
                float e[TOPK]; float tot = 0.f;
                #pragma unroll
                for (int k = 0; k < TOPK; k++) { e[k] = expf(safe[k] - m); tot += e[k]; }
                #pragma unroll
                for (int k = 0; k < TOPK; k++) { float w = e[k] / tot; swt[k] = w; sw_ += w; }
            }
            g_sw[bt] = sw_;
        }
    }
    __syncthreads();

    float acc = 0.f;
    #pragma unroll
    for (int k = 0; k < TOPK; k++) {
        float w = swt[k];
        if (w != 0.f) {
            int d = sidx[k];
            int n = d / L, l = d - n*L;
            int tp = t - c_lags[l];
            acc += w * peer[((size_t)((b*N + n)*T + tp)) * H + tid];
        }
    }
    g_agg[bt*H + tid] = acc;
}

// ===== cs_y = agg@wv^T + sw*bv ; FFN(elu) ; residual ; LayerNorm ; out ======
__global__ void k_ffn(const float* __restrict__ bv, const float* __restrict__ b1,
                      const float* __restrict__ b2, const float* __restrict__ gamma,
                      const float* __restrict__ beta, float* __restrict__ out) {
    __shared__ float s_xa[H*RB];        // transposed activations (buffer A)
    __shared__ float s_xb[H*RB];        // buffer B
    __shared__ float s_w[2][KK*H];
    __shared__ float s_sw[RB];
    __shared__ float s_ps[8][RB];       // LN partial sums
    __shared__ float s_pq[8][RB];       // LN partial sumsq
    __shared__ float s_mu[RB], s_rs[RB];

    int r0 = blockIdx.x * RB;
    int tid = threadIdx.x;
    int j = tid;
    int wid = tid >> 5, lane = tid & 31;

    // load agg transposed into s_xa
    {
        float v[RB];
        #pragma unroll
        for (int r = 0; r < RB; r++) v[r] = g_agg[(r0 + r)*H + tid];
        *(float4*)&s_xa[tid*RB]     = make_float4(v[0], v[1], v[2], v[3]);
        *(float4*)&s_xa[tid*RB + 4] = make_float4(v[4], v[5], v[6], v[7]);
    }
    if (tid < RB) s_sw[tid] = g_sw[r0 + tid];

    // ---- GEMM1: cs = agg @ wv^T + sw*bv ----
    float cs[RB];
    {
        float bvj = bv[j];
        #pragma unroll
        for (int r = 0; r < RB; r++) cs[r] = s_sw[r] * bvj;   // s_sw visible after GEMM8's first sync? No!
    }
    __syncthreads();   // make s_sw + s_xa visible before use (GEMM8 has its own sync but cs init reads s_sw)
    {
        float bvj = bv[j];
        #pragma unroll
        for (int r = 0; r < RB; r++) cs[r] = s_sw[r] * bvj;
        GEMM8(g_wvT, s_xa, s_w, cs);
    }
    // write cs transposed into s_xb (next GEMM's input)
    *(float4*)&s_xb[j*RB]     = make_float4(cs[0], cs[1], cs[2], cs[3]);
    *(float4*)&s_xb[j*RB + 4] = make_float4(cs[4], cs[5], cs[6], cs[7]);

    // ---- GEMM2: hidden = elu(cs @ w1^T + b1) ----
    float hd[RB];
    {
        float b1j = b1[j];
        #pragma unroll
        for (int r = 0; r < RB; r++) hd[r] = b1j;
        GEMM8(g_w1T, s_xb, s_w, hd);
        #pragma unroll
        for (int r = 0; r < RB; r++) hd[r] = hd[r] > 0.f ? hd[r] : expm1f(hd[r]);
    }
    // write hidden transposed into s_xa (agg dead)
    *(float4*)&s_xa[j*RB]     = make_float4(hd[0], hd[1], hd[2], hd[3]);
    *(float4*)&s_xa[j*RB + 4] = make_float4(hd[4], hd[5], hd[6], hd[7]);

    // ---- GEMM3: y = cs + hidden @ w2^T + b2 ----
    float y[RB];
    {
        float b2j = b2[j];
        #pragma unroll
        for (int r = 0; r < RB; r++) y[r] = b2j + cs[r];
        GEMM8(g_w2T, s_xa, s_w, y);
    }

    // ---- LayerNorm stats via shuffles ----
    #pragma unroll
    for (int r = 0; r < RB; r++) {
        float s = y[r], q = y[r]*y[r];
        for (int off = 16; off; off >>= 1) {
            s += __shfl_down_sync(0xffffffffu, s, off);
            q += __shfl_down_sync(0xffffffffu, q, off);
        }
        if (lane == 0) { s_ps[wid][r] = s; s_pq[wid][r] = q; }
    }
    __syncthreads();
    if (tid < RB) {
        float s = 0.f, q = 0.f;
        #pragma unroll
        for (int w = 0; w < 8; w++) { s += s_ps[w][tid]; q += s_pq[w][tid]; }
        float mu = s * (1.f/H);
        float var = q * (1.f/H) - mu*mu;
        s_mu[tid] = mu;
        s_rs[tid] = rsqrtf(var + 1e-5f);
    }
    __syncthreads();
    float gj = gamma[j], bj = beta[j];
    #pragma unroll
    for (int r = 0; r < RB; r++)
        out[(r0 + r)*H + j] = (y[r] - s_mu[r]) * s_rs[r] * gj + bj;
}

extern "C" void kernel_launch(void* const* d_in, const int* in_sizes, int n_in,
                              void* d_out, int out_size) {
    const float* target_h = (const float*)d_in[0];
    const float* peer_h   = (const float*)d_in[1];
    const int*   peer_mask = (const int*)d_in[2];
    const float* wq = (const float*)d_in[3];
    const float* bq = (const float*)d_in[4];
    const float* wk = (const float*)d_in[5];
    const float* bk = (const float*)d_in[6];
    const float* wv = (const float*)d_in[7];
    const float* bv = (const float*)d_in[8];
    const float* w1 = (const float*)d_in[9];
    const float* b1 = (const float*)d_in[10];
    const float* w2 = (const float*)d_in[11];
    const float* b2 = (const float*)d_in[12];
    const float* gamma = (const float*)d_in[13];
    const float* beta  = (const float*)d_in[14];
    float* out = (float*)d_out;

    k_prep<<<H + 3, 256>>>(wq, wk, bq, bk, wv, w1, w2);
    k_qtilde<<<BT/RB, 256>>>(target_h);
    k_logits<<<BT, 256>>>(peer_h, peer_mask);
    k_ffn<<<BT/RB, 256>>>(bv, b1, b2, gamma, beta, out);
}